// round 4
// baseline (speedup 1.0000x reference)
#include <cuda_runtime.h>
#include <cuda_fp16.h>
#include <cstdint>

namespace {

constexpr int THREADS = 256;
constexpr int NWARP   = 8;
constexpr int MT      = 2;               // 16-row m-tiles per warp
constexpr int WARP_M  = 16 * MT;         // 32 rows / warp
constexpr int CTA_M   = NWARP * WARP_M;  // 256 rows / CTA
constexpr int LDA     = 40;              // act smem ld (halves) - conflict-free
constexpr int LDST    = 20;              // f32 stage ld

struct SmemLayout {
    __half act[NWARP][WARP_M * LDA];        // 20480 B (input / concat staging only)
    float  stage[NWARP][MT * 16 * LDST];    // 20480 B (d1 out; reused for color out)
    float  sigma[NWARP][WARP_M];            //  1024 B
    __half w_d0[64 * 40];                   // B col-major: (k,n) -> n*LDB + k
    __half w_c0[64 * 40];
    __half w_d1[16 * 72];
    __half w_c3[16 * 72];
    __half w_c1[64 * 72];
    __half w_c2[64 * 72];
};  // ~75 KB -> 2 CTAs/SM

__device__ __forceinline__ uint32_t h2u(float x, float y) {
    __half2 h = __floats2half2_rn(x, y);
    return *reinterpret_cast<uint32_t*>(&h);
}

__device__ __forceinline__ void mma16816(float c[4], const uint32_t a[4],
                                         uint32_t b0, uint32_t b1) {
    asm volatile(
        "mma.sync.aligned.m16n8k16.row.col.f32.f16.f16.f32 "
        "{%0,%1,%2,%3},{%4,%5,%6,%7},{%8,%9},{%0,%1,%2,%3};\n"
        : "+f"(c[0]), "+f"(c[1]), "+f"(c[2]), "+f"(c[3])
        : "r"(a[0]), "r"(a[1]), "r"(a[2]), "r"(a[3]), "r"(b0), "r"(b1));
}

// Load one 16x16 matrix_a tile from row-major smem (conflict-free for LDA=40).
__device__ __forceinline__ void loadA(uint32_t a[4], const __half* p, int g, int i2) {
    a[0] = *reinterpret_cast<const uint32_t*>(p + g * LDA + i2);
    a[1] = *reinterpret_cast<const uint32_t*>(p + (g + 8) * LDA + i2);
    a[2] = *reinterpret_cast<const uint32_t*>(p + g * LDA + i2 + 8);
    a[3] = *reinterpret_cast<const uint32_t*>(p + (g + 8) * LDA + i2 + 8);
}

// Chained layer: A[MT][KT] (16x16 frags) x B(16KT x 16NPAIR*... 8*2*NPAIR cols)
// -> relu -> O[MT][NPAIR] matrix_a frags, all in registers.
// wg = w + g*LDB + i2 (per-lane base).
template <int KT, int NPAIR, int LDB>
__device__ __forceinline__ void layer_chain(const uint32_t (&A)[MT][KT][4],
                                            const __half* __restrict__ wg,
                                            uint32_t (&O)[MT][NPAIR][4]) {
#pragma unroll
    for (int np = 0; np < NPAIR; np++) {
        float acc[MT][2][4];
#pragma unroll
        for (int m = 0; m < MT; m++)
#pragma unroll
            for (int h = 0; h < 2; h++)
#pragma unroll
                for (int e = 0; e < 4; e++) acc[m][h][e] = 0.0f;
#pragma unroll
        for (int k = 0; k < KT; k++) {
#pragma unroll
            for (int h = 0; h < 2; h++) {
                const __half* bp = wg + (np * 16 + h * 8) * LDB + k * 16;
                uint32_t b0 = *reinterpret_cast<const uint32_t*>(bp);
                uint32_t b1 = *reinterpret_cast<const uint32_t*>(bp + 8);
#pragma unroll
                for (int m = 0; m < MT; m++) mma16816(acc[m][h], A[m][k], b0, b1);
            }
        }
        // D-pair -> next matrix_a fragment (relu + cvt in registers)
#pragma unroll
        for (int m = 0; m < MT; m++) {
            O[m][np][0] = h2u(fmaxf(acc[m][0][0], 0.f), fmaxf(acc[m][0][1], 0.f));
            O[m][np][1] = h2u(fmaxf(acc[m][0][2], 0.f), fmaxf(acc[m][0][3], 0.f));
            O[m][np][2] = h2u(fmaxf(acc[m][1][0], 0.f), fmaxf(acc[m][1][1], 0.f));
            O[m][np][3] = h2u(fmaxf(acc[m][1][2], 0.f), fmaxf(acc[m][1][3], 0.f));
        }
    }
}

}  // namespace

__global__ void __launch_bounds__(THREADS, 2)
nerf_fused_kernel(const float* __restrict__ hash, const float* __restrict__ sh,
                  const float* __restrict__ d0, const float* __restrict__ d1,
                  const float* __restrict__ c0, const float* __restrict__ c1,
                  const float* __restrict__ c2, const float* __restrict__ c3,
                  float* __restrict__ out, int n_tiles) {
    extern __shared__ char smem_raw[];
    SmemLayout& S = *reinterpret_cast<SmemLayout*>(smem_raw);
    const int tid  = threadIdx.x;
    const int warp = tid >> 5;
    const int lane = tid & 31;
    const int g    = lane >> 2;        // group id (row within tile half)
    const int i2   = (lane & 3) * 2;   // col pair base

    // ---- Stage weights to SMEM fp16 once per CTA ----
    for (int i = tid; i < 64 * 32; i += THREADS)
        S.w_d0[(i >> 5) * 40 + (i & 31)] = __float2half(d0[i]);
    for (int i = tid; i < 16 * 64; i += THREADS)
        S.w_d1[(i >> 6) * 72 + (i & 63)] = __float2half(d1[i]);
    for (int i = tid; i < 64 * 32; i += THREADS) {
        int n = i >> 5, k = i & 31;
        S.w_c0[n * 40 + k] = __float2half(k < 31 ? c0[n * 31 + k] : 0.0f);
    }
    for (int i = tid; i < 64 * 64; i += THREADS) {
        int n = i >> 6, k = i & 63;
        S.w_c1[n * 72 + k] = __float2half(c1[i]);
        S.w_c2[n * 72 + k] = __float2half(c2[i]);
    }
    for (int i = tid; i < 16 * 64; i += THREADS) {
        int n = i >> 6, k = i & 63;
        S.w_c3[n * 72 + k] = __float2half(n < 3 ? c3[n * 64 + k] : 0.0f);
    }
    __syncthreads();  // the ONLY block barrier

    __half* actw = S.act[warp];
    float*  stg  = S.stage[warp];
    float*  sig  = S.sigma[warp];
    const float4* hash4 = reinterpret_cast<const float4*>(hash);
    float4* out4 = reinterpret_cast<float4*>(out);

    const __half* wg_d0 = S.w_d0 + g * 40 + i2;
    const __half* wg_c0 = S.w_c0 + g * 40 + i2;
    const __half* wg_d1 = S.w_d1 + g * 72 + i2;
    const __half* wg_c3 = S.w_c3 + g * 72 + i2;
    const __half* wg_c1 = S.w_c1 + g * 72 + i2;
    const __half* wg_c2 = S.w_c2 + g * 72 + i2;

    for (int tile = blockIdx.x; tile < n_tiles; tile += gridDim.x) {
        const size_t row0 = (size_t)tile * CTA_M + warp * WARP_M;

        // ---- hash [32 x 32] f32 -> act half (coalesced) ----
#pragma unroll
        for (int idx = lane; idx < WARP_M * 8; idx += 32) {
            int r = idx >> 3, c = idx & 7;
            float4 v = hash4[(row0 + r) * 8 + c];
            __half2* dst = reinterpret_cast<__half2*>(actw + r * LDA + c * 4);
            dst[0] = __floats2half2_rn(v.x, v.y);
            dst[1] = __floats2half2_rn(v.z, v.w);
        }
        __syncwarp();

        uint32_t A32[MT][2][4];   // 32-wide activations (d0 / c0 inputs)
        uint32_t Aa[MT][4][4];    // 64-wide activations (ping)
        uint32_t Ab[MT][4][4];    // 64-wide activations (pong)

#pragma unroll
        for (int m = 0; m < MT; m++)
#pragma unroll
            for (int kt = 0; kt < 2; kt++)
                loadA(A32[m][kt], actw + m * 16 * LDA + kt * 16, g, i2);

        // ---- d0: [32x32]x[32x64] + relu, chained in registers ----
        layer_chain<2, 4, 40>(A32, wg_d0, Aa);

        // ---- d1: [32x64]x[64x16], f32 out -> stage + sigma ----
        {
            float dacc[MT][2][4];
#pragma unroll
            for (int m = 0; m < MT; m++)
#pragma unroll
                for (int h = 0; h < 2; h++)
#pragma unroll
                    for (int e = 0; e < 4; e++) dacc[m][h][e] = 0.0f;
#pragma unroll
            for (int k = 0; k < 4; k++) {
#pragma unroll
                for (int h = 0; h < 2; h++) {
                    const __half* bp = wg_d1 + h * 8 * 72 + k * 16;
                    uint32_t b0 = *reinterpret_cast<const uint32_t*>(bp);
                    uint32_t b1 = *reinterpret_cast<const uint32_t*>(bp + 8);
#pragma unroll
                    for (int m = 0; m < MT; m++) mma16816(dacc[m][h], Aa[m][k], b0, b1);
                }
            }
#pragma unroll
            for (int m = 0; m < MT; m++) {
                float* st = stg + m * 16 * LDST;
                st[g * LDST + i2]           = dacc[m][0][0];
                st[g * LDST + i2 + 1]       = dacc[m][0][1];
                st[(g + 8) * LDST + i2]     = dacc[m][0][2];
                st[(g + 8) * LDST + i2 + 1] = dacc[m][0][3];
                st[g * LDST + 8 + i2]       = dacc[m][1][0];
                st[g * LDST + 8 + i2 + 1]   = dacc[m][1][1];
                st[(g + 8) * LDST + 8 + i2] = dacc[m][1][2];
                st[(g + 8) * LDST + 8 + i2 + 1] = dacc[m][1][3];
                if (i2 == 0) {  // col 0 = sigma (f32, exact)
                    sig[m * 16 + g]     = dacc[m][0][0];
                    sig[m * 16 + g + 8] = dacc[m][0][2];
                }
            }
        }
        __syncwarp();

        // ---- pack act <- [sh(16) | density(15) | 0] ----
#pragma unroll
        for (int idx = lane; idx < WARP_M * 32; idx += 32) {
            int r = idx >> 5, c = idx & 31;
            const float* st = stg + (r >> 4) * 16 * LDST;
            float v;
            if (c < 16)      v = sh[(row0 + r) * 16 + c];
            else if (c < 31) v = st[(r & 15) * LDST + (c - 15)];
            else             v = 0.0f;
            actw[r * LDA + c] = __float2half(v);
        }
        __syncwarp();

#pragma unroll
        for (int m = 0; m < MT; m++)
#pragma unroll
            for (int kt = 0; kt < 2; kt++)
                loadA(A32[m][kt], actw + m * 16 * LDA + kt * 16, g, i2);

        // ---- c0, c1, c2: register-chained relu layers ----
        layer_chain<2, 4, 40>(A32, wg_c0, Aa);
        layer_chain<4, 4, 72>(Aa,  wg_c1, Ab);
        layer_chain<4, 4, 72>(Ab,  wg_c2, Aa);

        // ---- c3: [32x64]x[64x8(3 used)] -> color ----
        {
            float cacc[MT][4];
#pragma unroll
            for (int m = 0; m < MT; m++)
#pragma unroll
                for (int e = 0; e < 4; e++) cacc[m][e] = 0.0f;
#pragma unroll
            for (int k = 0; k < 4; k++) {
                const __half* bp = wg_c3 + k * 16;
                uint32_t b0 = *reinterpret_cast<const uint32_t*>(bp);
                uint32_t b1 = *reinterpret_cast<const uint32_t*>(bp + 8);
#pragma unroll
                for (int m = 0; m < MT; m++) mma16816(cacc[m], Aa[m][k], b0, b1);
            }
            // stage reused (dead after pack) as float4[32] color staging
            float4* ost = reinterpret_cast<float4*>(stg);
#pragma unroll
            for (int m = 0; m < MT; m++) {
                if (i2 == 0) {  // cols 0,1
                    ost[m * 16 + g].x     = cacc[m][0];
                    ost[m * 16 + g].y     = cacc[m][1];
                    ost[m * 16 + g + 8].x = cacc[m][2];
                    ost[m * 16 + g + 8].y = cacc[m][3];
                } else if (i2 == 2) {  // col 2
                    ost[m * 16 + g].z     = cacc[m][0];
                    ost[m * 16 + g + 8].z = cacc[m][2];
                }
            }
        }
        __syncwarp();

        // ---- out[p] = {r, g, b, sigma} ----
        {
            float4 o;
            o.x = stg[lane * 4 + 0];
            o.y = stg[lane * 4 + 1];
            o.z = stg[lane * 4 + 2];
            o.w = sig[lane];
            out4[row0 + lane] = o;
        }
        __syncwarp();
    }
}

extern "C" void kernel_launch(void* const* d_in, const int* in_sizes, int n_in,
                              void* d_out, int out_size) {
    const float* hash = (const float*)d_in[0];  // [N, 32]
    const float* sh   = (const float*)d_in[1];  // [N, 16]
    const float* d0   = (const float*)d_in[2];  // [64, 32]
    const float* d1   = (const float*)d_in[3];  // [16, 64]
    const float* c0   = (const float*)d_in[4];  // [64, 31]
    const float* c1   = (const float*)d_in[5];  // [64, 64]
    const float* c2   = (const float*)d_in[6];  // [64, 64]
    const float* c3   = (const float*)d_in[7];  // [3, 64]
    float* out = (float*)d_out;                 // [N, 4]

    const int n       = in_sizes[0] / 32;
    const int n_tiles = n / CTA_M;  // 8192

    cudaFuncSetAttribute(nerf_fused_kernel,
                         cudaFuncAttributeMaxDynamicSharedMemorySize,
                         (int)sizeof(SmemLayout));

    int grid = 296;  // persistent, 2 CTAs/SM
    if (grid > n_tiles) grid = n_tiles;

    nerf_fused_kernel<<<grid, THREADS, sizeof(SmemLayout)>>>(
        hash, sh, d0, d1, c0, c1, c2, c3, out, n_tiles);
}

// round 5
// speedup vs baseline: 1.9603x; 1.9603x over previous
#include <cuda_runtime.h>
#include <cuda_fp16.h>
#include <cstdint>

namespace {

constexpr int THREADS = 256;
constexpr int NWARP   = 8;
constexpr int CTA_M   = NWARP * 16;  // 128 rows / CTA, 16 per warp
constexpr int LDD     = 24;          // density smem ld (halves); stride 12 words
                                     // -> conflict-free for (g, i2) store pattern

struct SmemLayout {
    __half w_d0[64 * 40];   // B col-major: (k,n) -> n*LDB + k
    __half w_c0[64 * 40];
    __half w_d1[16 * 72];
    __half w_c3[16 * 72];
    __half w_c1[64 * 72];
    __half w_c2[64 * 72];
    __half den[NWARP][16 * LDD];  // d1 outputs (16 cols) for the concat shift
};  // ~39.4 KB static

__device__ __forceinline__ uint32_t h2u(float x, float y) {
    __half2 h = __floats2half2_rn(x, y);
    return *reinterpret_cast<uint32_t*>(&h);
}
__device__ __forceinline__ uint32_t hh2u(__half x, __half y) {
    __half2 h = __halves2half2(x, y);
    return *reinterpret_cast<uint32_t*>(&h);
}

__device__ __forceinline__ void mma16816(float c[4], const uint32_t a[4],
                                         uint32_t b0, uint32_t b1) {
    asm volatile(
        "mma.sync.aligned.m16n8k16.row.col.f32.f16.f16.f32 "
        "{%0,%1,%2,%3},{%4,%5,%6,%7},{%8,%9},{%0,%1,%2,%3};\n"
        : "+f"(c[0]), "+f"(c[1]), "+f"(c[2]), "+f"(c[3])
        : "r"(a[0]), "r"(a[1]), "r"(a[2]), "r"(a[3]), "r"(b0), "r"(b1));
}

// Register-chained relu layer: A[KT] 16x16 frags -> O[NPAIR] 16x16 frags.
// wg is the per-lane weight base (w + g*LDB + i2).
template <int KT, int NPAIR, int LDB>
__device__ __forceinline__ void layer_chain(const uint32_t (&A)[KT][4],
                                            const __half* __restrict__ wg,
                                            uint32_t (&O)[NPAIR][4]) {
#pragma unroll
    for (int np = 0; np < NPAIR; np++) {
        float acc[2][4];
#pragma unroll
        for (int h = 0; h < 2; h++)
#pragma unroll
            for (int e = 0; e < 4; e++) acc[h][e] = 0.0f;
#pragma unroll
        for (int k = 0; k < KT; k++) {
#pragma unroll
            for (int h = 0; h < 2; h++) {
                const __half* bp = wg + (np * 16 + h * 8) * LDB + k * 16;
                uint32_t b0 = *reinterpret_cast<const uint32_t*>(bp);
                uint32_t b1 = *reinterpret_cast<const uint32_t*>(bp + 8);
                mma16816(acc[h], A[k], b0, b1);
            }
        }
        O[np][0] = h2u(fmaxf(acc[0][0], 0.f), fmaxf(acc[0][1], 0.f));
        O[np][1] = h2u(fmaxf(acc[0][2], 0.f), fmaxf(acc[0][3], 0.f));
        O[np][2] = h2u(fmaxf(acc[1][0], 0.f), fmaxf(acc[1][1], 0.f));
        O[np][3] = h2u(fmaxf(acc[1][2], 0.f), fmaxf(acc[1][3], 0.f));
    }
}

}  // namespace

__global__ void __launch_bounds__(THREADS, 3)
nerf_fused_kernel(const float* __restrict__ hash, const float* __restrict__ sh,
                  const float* __restrict__ d0, const float* __restrict__ d1,
                  const float* __restrict__ c0, const float* __restrict__ c1,
                  const float* __restrict__ c2, const float* __restrict__ c3,
                  float* __restrict__ out, int n_tiles) {
    __shared__ SmemLayout S;
    const int tid  = threadIdx.x;
    const int warp = tid >> 5;
    const int lane = tid & 31;
    const int g    = lane >> 2;       // row-in-tile-half
    const int i2   = (lane & 3) * 2;  // column pair base

    // ---- Stage weights to SMEM fp16 once per CTA ----
    for (int i = tid; i < 64 * 32; i += THREADS)
        S.w_d0[(i >> 5) * 40 + (i & 31)] = __float2half(d0[i]);
    for (int i = tid; i < 16 * 64; i += THREADS)
        S.w_d1[(i >> 6) * 72 + (i & 63)] = __float2half(d1[i]);
    for (int i = tid; i < 64 * 32; i += THREADS) {
        int n = i >> 5, k = i & 31;
        S.w_c0[n * 40 + k] = __float2half(k < 31 ? c0[n * 31 + k] : 0.0f);
    }
    for (int i = tid; i < 64 * 64; i += THREADS) {
        int n = i >> 6, k = i & 63;
        S.w_c1[n * 72 + k] = __float2half(c1[i]);
        S.w_c2[n * 72 + k] = __float2half(c2[i]);
    }
    for (int i = tid; i < 16 * 64; i += THREADS) {
        int n = i >> 6, k = i & 63;
        S.w_c3[n * 72 + k] = __float2half(n < 3 ? c3[n * 64 + k] : 0.0f);
    }
    __syncthreads();  // only block barrier

    __half* den = S.den[warp];
    const __half* wg_d0 = S.w_d0 + g * 40 + i2;
    const __half* wg_c0 = S.w_c0 + g * 40 + i2;
    const __half* wg_d1 = S.w_d1 + g * 72 + i2;
    const __half* wg_c3 = S.w_c3 + g * 72 + i2;
    const __half* wg_c1 = S.w_c1 + g * 72 + i2;
    const __half* wg_c2 = S.w_c2 + g * 72 + i2;
    float4* out4 = reinterpret_cast<float4*>(out);

    for (int tile = blockIdx.x; tile < n_tiles; tile += gridDim.x) {
        const size_t row0 = (size_t)tile * CTA_M + warp * 16;

        // ---- A frags for d0 straight from gmem (8B loads, sectors fully used)
        uint32_t Aa[4][4];  // 64-wide ping
        uint32_t Ab[4][4];  // 64-wide pong (Ab[0..1] doubles as 32-wide input)
        {
            const float* h0 = hash + (row0 + g) * 32;
            const float* h8 = hash + (row0 + g + 8) * 32;
#pragma unroll
            for (int kt = 0; kt < 2; kt++) {
                Ab[kt][0] = h2u(h0[kt * 16 + i2],     h0[kt * 16 + i2 + 1]);
                Ab[kt][1] = h2u(h8[kt * 16 + i2],     h8[kt * 16 + i2 + 1]);
                Ab[kt][2] = h2u(h0[kt * 16 + i2 + 8], h0[kt * 16 + i2 + 9]);
                Ab[kt][3] = h2u(h8[kt * 16 + i2 + 8], h8[kt * 16 + i2 + 9]);
            }
        }

        // ---- d0: relu(hash @ d0^T), chained ----
        {
            uint32_t A32[2][4] = {{Ab[0][0], Ab[0][1], Ab[0][2], Ab[0][3]},
                                  {Ab[1][0], Ab[1][1], Ab[1][2], Ab[1][3]}};
            layer_chain<2, 4, 40>(A32, wg_d0, Aa);
        }

        // ---- d1: h @ d1^T -> sigma (regs) + density (smem half) ----
        float sig0, sig1;
        {
            float dacc[2][4];
#pragma unroll
            for (int h = 0; h < 2; h++)
#pragma unroll
                for (int e = 0; e < 4; e++) dacc[h][e] = 0.0f;
#pragma unroll
            for (int k = 0; k < 4; k++) {
#pragma unroll
                for (int h = 0; h < 2; h++) {
                    const __half* bp = wg_d1 + h * 8 * 72 + k * 16;
                    uint32_t b0 = *reinterpret_cast<const uint32_t*>(bp);
                    uint32_t b1 = *reinterpret_cast<const uint32_t*>(bp + 8);
                    mma16816(dacc[h], Aa[k], b0, b1);
                }
            }
            sig0 = dacc[0][0];  // valid on i2==0 lanes (col 0 = sigma)
            sig1 = dacc[0][2];
            *reinterpret_cast<uint32_t*>(den + g * LDD + i2) =
                h2u(dacc[0][0], dacc[0][1]);
            *reinterpret_cast<uint32_t*>(den + (g + 8) * LDD + i2) =
                h2u(dacc[0][2], dacc[0][3]);
            *reinterpret_cast<uint32_t*>(den + g * LDD + i2 + 8) =
                h2u(dacc[1][0], dacc[1][1]);
            *reinterpret_cast<uint32_t*>(den + (g + 8) * LDD + i2 + 8) =
                h2u(dacc[1][2], dacc[1][3]);
        }
        __syncwarp();

        // ---- c0 input: k-tile0 = sh (gmem), k-tile1 = shifted density ----
        {
            const float* s0 = sh + (row0 + g) * 16;
            const float* s8 = sh + (row0 + g + 8) * 16;
            uint32_t A32[2][4];
            A32[0][0] = h2u(s0[i2],     s0[i2 + 1]);
            A32[0][1] = h2u(s8[i2],     s8[i2 + 1]);
            A32[0][2] = h2u(s0[i2 + 8], s0[i2 + 9]);
            A32[0][3] = h2u(s8[i2 + 8], s8[i2 + 9]);
            // concat col 16+j = d1col j+1 (shift by one); col 31 -> 0
            __half z = __float2half(0.0f);
            __half hiA = (i2 == 6) ? z : den[g * LDD + i2 + 10];
            __half hiB = (i2 == 6) ? z : den[(g + 8) * LDD + i2 + 10];
            A32[1][0] = hh2u(den[g * LDD + i2 + 1],       den[g * LDD + i2 + 2]);
            A32[1][1] = hh2u(den[(g + 8) * LDD + i2 + 1], den[(g + 8) * LDD + i2 + 2]);
            A32[1][2] = hh2u(den[g * LDD + i2 + 9],       hiA);
            A32[1][3] = hh2u(den[(g + 8) * LDD + i2 + 9], hiB);

            layer_chain<2, 4, 40>(A32, wg_c0, Aa);
        }

        // ---- c1, c2: chained ----
        layer_chain<4, 4, 72>(Aa, wg_c1, Ab);
        layer_chain<4, 4, 72>(Ab, wg_c2, Aa);

        // ---- c3: color (cols 0..2 of an 8-wide n-tile) ----
        {
            float cacc[4] = {0.f, 0.f, 0.f, 0.f};
#pragma unroll
            for (int k = 0; k < 4; k++) {
                const __half* bp = wg_c3 + k * 16;
                uint32_t b0 = *reinterpret_cast<const uint32_t*>(bp);
                uint32_t b1 = *reinterpret_cast<const uint32_t*>(bp + 8);
                mma16816(cacc, Aa[k], b0, b1);
            }
            // lane 4g   holds cols {0,1}; lane 4g+1 holds col 2
            float b0c = __shfl_down_sync(0xffffffffu, cacc[0], 1);
            float b1c = __shfl_down_sync(0xffffffffu, cacc[2], 1);
            if ((lane & 3) == 0) {
                out4[row0 + g]     = make_float4(cacc[0], cacc[1], b0c, sig0);
                out4[row0 + g + 8] = make_float4(cacc[2], cacc[3], b1c, sig1);
            }
        }
    }
}

extern "C" void kernel_launch(void* const* d_in, const int* in_sizes, int n_in,
                              void* d_out, int out_size) {
    const float* hash = (const float*)d_in[0];  // [N, 32]
    const float* sh   = (const float*)d_in[1];  // [N, 16]
    const float* d0   = (const float*)d_in[2];  // [64, 32]
    const float* d1   = (const float*)d_in[3];  // [16, 64]
    const float* c0   = (const float*)d_in[4];  // [64, 31]
    const float* c1   = (const float*)d_in[5];  // [64, 64]
    const float* c2   = (const float*)d_in[6];  // [64, 64]
    const float* c3   = (const float*)d_in[7];  // [3, 64]
    float* out = (float*)d_out;                 // [N, 4]

    const int n       = in_sizes[0] / 32;
    const int n_tiles = n / CTA_M;  // 16384

    int grid = 148 * 3;  // persistent, 3 CTAs/SM (85-reg budget)
    if (grid > n_tiles) grid = n_tiles;

    nerf_fused_kernel<<<grid, THREADS>>>(hash, sh, d0, d1, c0, c1, c2, c3, out,
                                         n_tiles);
}